// round 3
// baseline (speedup 1.0000x reference)
#include <cuda_runtime.h>
#include <cuda_bf16.h>
#include <cstdint>

#define N_NODES 50000
#define D_FEAT  64
#define H_FEAT  128
#define MAX_DEG 96

// Scratch: padded adjacency + per-node degree counters
__device__ int g_cnt[N_NODES];
__device__ int g_adj[(size_t)N_NODES * MAX_DEG];

// ---------------------------------------------------------------------------
// Kernel 1: zero degree counters
// ---------------------------------------------------------------------------
__global__ void zero_cnt_kernel(int n) {
    int i = blockIdx.x * blockDim.x + threadIdx.x;
    if (i < n) g_cnt[i] = 0;
}

// ---------------------------------------------------------------------------
// Kernel 2: build padded adjacency. One thread per edge.
//   adj[s] gets d, adj[d] gets s.
// ---------------------------------------------------------------------------
__global__ void fill_adj_kernel(const int* __restrict__ ei, int E, int N) {
    int e = blockIdx.x * blockDim.x + threadIdx.x;
    if (e >= E) return;
    int s = ei[e];
    int d = ei[(size_t)E + e];
    if ((unsigned)s >= (unsigned)N || (unsigned)d >= (unsigned)N) return;

    int ps = atomicAdd(&g_cnt[s], 1);
    if (ps < MAX_DEG) g_adj[(size_t)s * MAX_DEG + ps] = d;
    int pd = atomicAdd(&g_cnt[d], 1);
    if (pd < MAX_DEG) g_adj[(size_t)d * MAX_DEG + pd] = s;
}

// ---------------------------------------------------------------------------
// Kernel 3: fused gather-aggregate + GIN MLP.
// Block = 256 threads handles NT=32 nodes.
//   Phase 0: warp w aggregates nodes w*4..w*4+3 (neighbor gather, float2/lane),
//            acc = (1+eps)*x[n] + sum_{nbr} x[nbr], written transposed to smem.
//   Phase 1: GEMM1 (4x4 reg tile) -> relu -> smem
//   Phase 2: GEMM2 (2x4 reg tile) -> out
// ---------------------------------------------------------------------------
#define NT 32
#define VP 33

__global__ __launch_bounds__(256, 4)
void agg_mlp_kernel(const float* __restrict__ x,
                    const float* __restrict__ eps,
                    const float* __restrict__ W1, const float* __restrict__ b1,
                    const float* __restrict__ W2, const float* __restrict__ b2,
                    float* __restrict__ out, int N) {
    __shared__ float Vt[D_FEAT * VP];   // Vt[k][n]
    __shared__ float Ht[H_FEAT * VP];   // Ht[j][n]

    const int t    = threadIdx.x;
    const int lane = t & 31;
    const int w    = t >> 5;
    const int n0   = blockIdx.x * NT;
    const float se = 1.0f + __ldg(eps);

    // ---- Phase 0: aggregate (warp per node, 4 nodes per warp) ----
    #pragma unroll
    for (int i = 0; i < 4; i++) {
        const int n    = w * 4 + i;
        const int node = n0 + n;
        float a0 = 0.f, a1 = 0.f, c0acc = 0.f, c1acc = 0.f;

        if (node < N) {
            int deg = g_cnt[node];
            deg = (deg > MAX_DEG) ? MAX_DEG : deg;
            const int* base = g_adj + (size_t)node * MAX_DEG;
            // preload neighbor ids into lanes (3 chunks of 32)
            int id0 = (lane      < deg) ? base[lane]      : 0;
            int id1 = (lane + 32 < deg) ? base[lane + 32] : 0;
            int id2 = (lane + 64 < deg) ? base[lane + 64] : 0;

            const float* xk = x + 2 * lane;

            int jend0 = (deg < 32) ? deg : 32;
            for (int j = 0; j < jend0; j += 2) {
                int nb0 = __shfl_sync(0xffffffffu, id0, j);
                float2 v0 = *reinterpret_cast<const float2*>(xk + (size_t)nb0 * D_FEAT);
                a0 += v0.x; a1 += v0.y;
                if (j + 1 < jend0) {
                    int nb1 = __shfl_sync(0xffffffffu, id0, j + 1);
                    float2 v1 = *reinterpret_cast<const float2*>(xk + (size_t)nb1 * D_FEAT);
                    c0acc += v1.x; c1acc += v1.y;
                }
            }
            if (deg > 32) {
                int jend1 = ((deg - 32) < 32) ? (deg - 32) : 32;
                for (int j = 0; j < jend1; j += 2) {
                    int nb0 = __shfl_sync(0xffffffffu, id1, j);
                    float2 v0 = *reinterpret_cast<const float2*>(xk + (size_t)nb0 * D_FEAT);
                    a0 += v0.x; a1 += v0.y;
                    if (j + 1 < jend1) {
                        int nb1 = __shfl_sync(0xffffffffu, id1, j + 1);
                        float2 v1 = *reinterpret_cast<const float2*>(xk + (size_t)nb1 * D_FEAT);
                        c0acc += v1.x; c1acc += v1.y;
                    }
                }
            }
            if (deg > 64) {
                int jend2 = deg - 64;
                for (int j = 0; j < jend2; j += 2) {
                    int nb0 = __shfl_sync(0xffffffffu, id2, j);
                    float2 v0 = *reinterpret_cast<const float2*>(xk + (size_t)nb0 * D_FEAT);
                    a0 += v0.x; a1 += v0.y;
                    if (j + 1 < jend2) {
                        int nb1 = __shfl_sync(0xffffffffu, id2, j + 1);
                        float2 v1 = *reinterpret_cast<const float2*>(xk + (size_t)nb1 * D_FEAT);
                        c0acc += v1.x; c1acc += v1.y;
                    }
                }
            }
            // self term
            float2 xs = *reinterpret_cast<const float2*>(xk + (size_t)node * D_FEAT);
            a0 += c0acc + se * xs.x;
            a1 += c1acc + se * xs.y;
        }
        Vt[(2 * lane)     * VP + n] = a0;
        Vt[(2 * lane + 1) * VP + n] = a1;
    }
    __syncthreads();

    // ---- Phase 1: GEMM1  H[NT][128] = relu(V @ W1 + b1) ----
    {
        const int tx = t & 31;       // 32 * 4 = 128 j-columns
        const int ty = t >> 5;       // 8 * 4 = 32 nodes
        const int j4 = tx * 4;
        const int nb = ty * 4;

        float a[4][4];
        float4 bb = *reinterpret_cast<const float4*>(b1 + j4);
        #pragma unroll
        for (int i = 0; i < 4; i++) {
            a[i][0] = bb.x; a[i][1] = bb.y; a[i][2] = bb.z; a[i][3] = bb.w;
        }

        #pragma unroll 8
        for (int k = 0; k < D_FEAT; k++) {
            float4 ww = *reinterpret_cast<const float4*>(W1 + k * H_FEAT + j4);
            float v0 = Vt[k * VP + nb + 0];
            float v1 = Vt[k * VP + nb + 1];
            float v2 = Vt[k * VP + nb + 2];
            float v3 = Vt[k * VP + nb + 3];
            a[0][0] = fmaf(v0, ww.x, a[0][0]); a[0][1] = fmaf(v0, ww.y, a[0][1]);
            a[0][2] = fmaf(v0, ww.z, a[0][2]); a[0][3] = fmaf(v0, ww.w, a[0][3]);
            a[1][0] = fmaf(v1, ww.x, a[1][0]); a[1][1] = fmaf(v1, ww.y, a[1][1]);
            a[1][2] = fmaf(v1, ww.z, a[1][2]); a[1][3] = fmaf(v1, ww.w, a[1][3]);
            a[2][0] = fmaf(v2, ww.x, a[2][0]); a[2][1] = fmaf(v2, ww.y, a[2][1]);
            a[2][2] = fmaf(v2, ww.z, a[2][2]); a[2][3] = fmaf(v2, ww.w, a[2][3]);
            a[3][0] = fmaf(v3, ww.x, a[3][0]); a[3][1] = fmaf(v3, ww.y, a[3][1]);
            a[3][2] = fmaf(v3, ww.z, a[3][2]); a[3][3] = fmaf(v3, ww.w, a[3][3]);
        }

        #pragma unroll
        for (int jj = 0; jj < 4; jj++)
            #pragma unroll
            for (int i = 0; i < 4; i++)
                Ht[(j4 + jj) * VP + nb + i] = fmaxf(a[i][jj], 0.0f);
    }
    __syncthreads();

    // ---- Phase 2: GEMM2  Y[NT][64] = H @ W2 + b2 ----
    {
        const int tx = t & 15;       // 16 * 4 = 64 d-columns
        const int ty = t >> 4;       // 16 * 2 = 32 nodes
        const int d4 = tx * 4;
        const int nb = ty * 2;

        float a[2][4];
        float4 bb = *reinterpret_cast<const float4*>(b2 + d4);
        a[0][0] = bb.x; a[0][1] = bb.y; a[0][2] = bb.z; a[0][3] = bb.w;
        a[1][0] = bb.x; a[1][1] = bb.y; a[1][2] = bb.z; a[1][3] = bb.w;

        #pragma unroll 8
        for (int j = 0; j < H_FEAT; j++) {
            float4 ww = *reinterpret_cast<const float4*>(W2 + j * D_FEAT + d4);
            float v0 = Ht[j * VP + nb + 0];
            float v1 = Ht[j * VP + nb + 1];
            a[0][0] = fmaf(v0, ww.x, a[0][0]); a[0][1] = fmaf(v0, ww.y, a[0][1]);
            a[0][2] = fmaf(v0, ww.z, a[0][2]); a[0][3] = fmaf(v0, ww.w, a[0][3]);
            a[1][0] = fmaf(v1, ww.x, a[1][0]); a[1][1] = fmaf(v1, ww.y, a[1][1]);
            a[1][2] = fmaf(v1, ww.z, a[1][2]); a[1][3] = fmaf(v1, ww.w, a[1][3]);
        }

        #pragma unroll
        for (int i = 0; i < 2; i++) {
            int node = n0 + nb + i;
            if (node < N) {
                float4 y = make_float4(a[i][0], a[i][1], a[i][2], a[i][3]);
                *reinterpret_cast<float4*>(out + (size_t)node * D_FEAT + d4) = y;
            }
        }
    }
}

// ---------------------------------------------------------------------------
// Launch
// ---------------------------------------------------------------------------
extern "C" void kernel_launch(void* const* d_in, const int* in_sizes, int n_in,
                              void* d_out, int out_size) {
    const float* x   = (const float*)d_in[0];
    const float* W1  = (const float*)d_in[1];
    const float* b1  = (const float*)d_in[2];
    const float* W2  = (const float*)d_in[3];
    const float* b2  = (const float*)d_in[4];
    const float* eps = (const float*)d_in[5];
    const int*   ei  = (const int*)d_in[6];     // edge_index as int32
    float* out = (float*)d_out;

    const int N = in_sizes[0] / D_FEAT;     // 50000
    const int E = in_sizes[6] / 2;          // 800000

    zero_cnt_kernel<<<(N + 255) / 256, 256>>>(N);
    fill_adj_kernel<<<(E + 255) / 256, 256>>>(ei, E, N);
    agg_mlp_kernel<<<(N + NT - 1) / NT, 256>>>(x, eps, W1, b1, W2, b2, out, N);
}

// round 5
// speedup vs baseline: 1.2156x; 1.2156x over previous
#include <cuda_runtime.h>
#include <cuda_bf16.h>
#include <cstdint>

#define N_NODES 50000
#define D_FEAT  64
#define H_FEAT  128

// Scratch accumulator: acc = (1+eps)*x + neighbor-sum  (12.8 MB)
__device__ float g_acc[(size_t)N_NODES * D_FEAT];

// ---- packed f32x2 helpers -------------------------------------------------
#define FMA2(d, a, b, c) \
    asm("fma.rn.f32x2 %0, %1, %2, %3;" : "=l"(d) : "l"(a), "l"(b), "l"(c))
#define PACK2(d, lo, hi) \
    asm("mov.b64 %0, {%1, %2};" : "=l"(d) : "f"(lo), "f"(hi))
#define UNPACK2(lo, hi, s) \
    asm("mov.b64 {%0, %1}, %2;" : "=f"(lo), "=f"(hi) : "l"(s))

// ---------------------------------------------------------------------------
// Kernel 1: acc[i] = (1+eps) * x[i]
// ---------------------------------------------------------------------------
__global__ void init_acc_kernel(const float* __restrict__ x,
                                const float* __restrict__ eps,
                                int total4) {
    int i = blockIdx.x * blockDim.x + threadIdx.x;
    if (i >= total4) return;
    float s = 1.0f + eps[0];
    float4 v = reinterpret_cast<const float4*>(x)[i];
    v.x *= s; v.y *= s; v.z *= s; v.w *= s;
    reinterpret_cast<float4*>(g_acc)[i] = v;
}

// ---------------------------------------------------------------------------
// Kernel 2: edge scatter. 16 lanes per edge; lane c handles float4 chunk c.
// ---------------------------------------------------------------------------
__global__ void scatter_kernel(const float* __restrict__ x,
                               const int* __restrict__ ei,
                               int E, int N) {
    int t = blockIdx.x * blockDim.x + threadIdx.x;
    int e = t >> 4;
    if (e >= E) return;
    int c = (t & 15) << 2;

    int s = ei[e];
    int d = ei[(size_t)E + e];
    if ((unsigned)s >= (unsigned)N || (unsigned)d >= (unsigned)N) return;

    const float4 vs = *reinterpret_cast<const float4*>(x + (size_t)s * D_FEAT + c);
    const float4 vd = *reinterpret_cast<const float4*>(x + (size_t)d * D_FEAT + c);

    float* as = g_acc + (size_t)s * D_FEAT + c;
    float* ad = g_acc + (size_t)d * D_FEAT + c;

    asm volatile("red.global.add.v4.f32 [%0], {%1, %2, %3, %4};"
                 :: "l"(as), "f"(vd.x), "f"(vd.y), "f"(vd.z), "f"(vd.w)
                 : "memory");
    asm volatile("red.global.add.v4.f32 [%0], {%1, %2, %3, %4};"
                 :: "l"(ad), "f"(vs.x), "f"(vs.y), "f"(vs.z), "f"(vs.w)
                 : "memory");
}

// ---------------------------------------------------------------------------
// Kernel 3: fused GIN MLP with packed f32x2 math (scalar LDS, packed FMA).
// ---------------------------------------------------------------------------
#define NT 32
#define VP 33

__global__ __launch_bounds__(256, 4)
void mlp_kernel(const float* __restrict__ W1, const float* __restrict__ b1,
                const float* __restrict__ W2, const float* __restrict__ b2,
                float* __restrict__ out, int N) {
    __shared__ float Vt[D_FEAT * VP];   // Vt[k][n]
    __shared__ float Ht[H_FEAT * VP];   // Ht[j][n]

    const int t  = threadIdx.x;
    const int n0 = blockIdx.x * NT;

    // ---- stage V (transposed) ----
    for (int idx = t; idx < NT * D_FEAT; idx += 256) {
        int n = idx >> 6;
        int k = idx & 63;
        int node = n0 + n;
        Vt[k * VP + n] = (node < N) ? g_acc[(size_t)node * D_FEAT + k] : 0.0f;
    }
    __syncthreads();

    // ---- GEMM1: H[NT][128] = relu(V @ W1 + b1) ----
    {
        const int tx = t & 31;       // 32 * 4 = 128 j-columns
        const int ty = t >> 5;       // 8 * 4 = 32 nodes
        const int j4 = tx * 4;
        const int nb = ty * 4;

        unsigned long long a2[4][2];   // [node][pair]
        {
            ulonglong2 bb = *reinterpret_cast<const ulonglong2*>(b1 + j4);
            #pragma unroll
            for (int i = 0; i < 4; i++) { a2[i][0] = bb.x; a2[i][1] = bb.y; }
        }

        #pragma unroll 8
        for (int k = 0; k < D_FEAT; k++) {
            ulonglong2 w = *reinterpret_cast<const ulonglong2*>(W1 + k * H_FEAT + j4);
            float s0 = Vt[k * VP + nb + 0];
            float s1 = Vt[k * VP + nb + 1];
            float s2 = Vt[k * VP + nb + 2];
            float s3 = Vt[k * VP + nb + 3];
            unsigned long long v0, v1, v2, v3;
            PACK2(v0, s0, s0);
            PACK2(v1, s1, s1);
            PACK2(v2, s2, s2);
            PACK2(v3, s3, s3);
            FMA2(a2[0][0], v0, w.x, a2[0][0]); FMA2(a2[0][1], v0, w.y, a2[0][1]);
            FMA2(a2[1][0], v1, w.x, a2[1][0]); FMA2(a2[1][1], v1, w.y, a2[1][1]);
            FMA2(a2[2][0], v2, w.x, a2[2][0]); FMA2(a2[2][1], v2, w.y, a2[2][1]);
            FMA2(a2[3][0], v3, w.x, a2[3][0]); FMA2(a2[3][1], v3, w.y, a2[3][1]);
        }

        #pragma unroll
        for (int i = 0; i < 4; i++) {
            float l0, h0, l1, h1;
            UNPACK2(l0, h0, a2[i][0]);
            UNPACK2(l1, h1, a2[i][1]);
            Ht[(j4 + 0) * VP + nb + i] = fmaxf(l0, 0.0f);
            Ht[(j4 + 1) * VP + nb + i] = fmaxf(h0, 0.0f);
            Ht[(j4 + 2) * VP + nb + i] = fmaxf(l1, 0.0f);
            Ht[(j4 + 3) * VP + nb + i] = fmaxf(h1, 0.0f);
        }
    }
    __syncthreads();

    // ---- GEMM2: Y[NT][64] = H @ W2 + b2 ----
    {
        const int tx = t & 15;       // 16 * 4 = 64 d-columns
        const int ty = t >> 4;       // 16 * 2 = 32 nodes
        const int d4 = tx * 4;
        const int nb = ty * 2;

        unsigned long long a2[2][2];
        {
            ulonglong2 bb = *reinterpret_cast<const ulonglong2*>(b2 + d4);
            a2[0][0] = bb.x; a2[0][1] = bb.y;
            a2[1][0] = bb.x; a2[1][1] = bb.y;
        }

        #pragma unroll 8
        for (int j = 0; j < H_FEAT; j++) {
            ulonglong2 w = *reinterpret_cast<const ulonglong2*>(W2 + j * D_FEAT + d4);
            float s0 = Ht[j * VP + nb + 0];
            float s1 = Ht[j * VP + nb + 1];
            unsigned long long v0, v1;
            PACK2(v0, s0, s0);
            PACK2(v1, s1, s1);
            FMA2(a2[0][0], v0, w.x, a2[0][0]); FMA2(a2[0][1], v0, w.y, a2[0][1]);
            FMA2(a2[1][0], v1, w.x, a2[1][0]); FMA2(a2[1][1], v1, w.y, a2[1][1]);
        }

        #pragma unroll
        for (int i = 0; i < 2; i++) {
            int node = n0 + nb + i;
            if (node < N) {
                ulonglong2 y;
                y.x = a2[i][0];
                y.y = a2[i][1];
                *reinterpret_cast<ulonglong2*>(out + (size_t)node * D_FEAT + d4) = y;
            }
        }
    }
}

// ---------------------------------------------------------------------------
// Launch
// ---------------------------------------------------------------------------
extern "C" void kernel_launch(void* const* d_in, const int* in_sizes, int n_in,
                              void* d_out, int out_size) {
    const float* x   = (const float*)d_in[0];
    const float* W1  = (const float*)d_in[1];
    const float* b1  = (const float*)d_in[2];
    const float* W2  = (const float*)d_in[3];
    const float* b2  = (const float*)d_in[4];
    const float* eps = (const float*)d_in[5];
    const int*   ei  = (const int*)d_in[6];
    float* out = (float*)d_out;

    const int N = in_sizes[0] / D_FEAT;     // 50000
    const int E = in_sizes[6] / 2;          // 800000

    int total4 = N * D_FEAT / 4;
    init_acc_kernel<<<(total4 + 255) / 256, 256>>>(x, eps, total4);

    long long threads = (long long)E * 16;
    int blocks = (int)((threads + 255) / 256);
    scatter_kernel<<<blocks, 256>>>(x, ei, E, N);

    mlp_kernel<<<(N + NT - 1) / NT, 256>>>(W1, b1, W2, b2, out, N);
}